// round 14
// baseline (speedup 1.0000x reference)
#include <cuda_runtime.h>

constexpr int B_ = 8192;
constexpr int K_ = 32;
constexpr int D_ = 129;
constexpr int V_ = 2048;
constexpr int KTOP = 10;
constexpr float WEIGHT_ = 0.15f;

constexpr int NBLK  = 740;          // ~one resident wave at 5 blocks/SM on 148 SMs
constexpr int NTHR  = 256;
constexpr int NWARP = NBLK * (NTHR / 32);   // 5920
constexpr int NITEM = B_ * 4;               // 32768 (row, group) items
constexpr int NCHUNK = 128;                 // 64 rows per chunk

// device scratch (zero-initialized at module load; self-resetting per launch)
__device__ float g_d[B_ * 33];
__device__ float g_loss[B_];
__device__ float g_chunk[NCHUNK];
__device__ int   g_rowcnt[B_];
__device__ int   g_chunkcnt[NCHUNK];
__device__ int   g_ccnt;

__device__ __forceinline__ float warp_sum(float v) {
#pragma unroll
    for (int o = 16; o; o >>= 1) v += __shfl_xor_sync(0xffffffffu, v, o);
    return v;
}
__device__ __forceinline__ float warp_max(float v) {
#pragma unroll
    for (int o = 16; o; o >>= 1) v = fmaxf(v, __shfl_xor_sync(0xffffffffu, v, o));
    return v;
}
__device__ __forceinline__ float acoshd(float x) {
    x = fmaxf(x, 1.0f + 1e-7f);
    return __logf(x + sqrtf(fmaf(x, x, -1.0f)));
}
__device__ __forceinline__ float inv_log2(float n) {
    return __fdividef(1.0f, __log2f(n));
}
__device__ __forceinline__ float pair_term(float ri, float ci, float di,
                                           float rj, float cj, float dj,
                                           float inv_idcg) {
    float drel  = ri - rj;
    float delta = fabsf(drel * (ci - cj)) * inv_idcg;
    float dd    = dj - di;
    float s     = (drel > 0.0f) ? 1.0f : -1.0f;
    float x     = s * dd;
    float sig   = __fdividef(1.0f, 1.0f + __expf(-x));
    return s * delta * sig * (-dd);
}

// 8-item tile: fold 32->8 lanes, transpose-reduce; returns total of item
// (lane & 7), replicated across the four octets. (verified exact R5/R11/R12)
__device__ __forceinline__ float tile_reduce8(float q[8], int lane) {
#pragma unroll
    for (int k = 0; k < 8; k++) {
        q[k] += __shfl_xor_sync(0xffffffffu, q[k], 16);
        q[k] += __shfl_xor_sync(0xffffffffu, q[k], 8);
    }
    const int ll = lane & 7;
#pragma unroll
    for (int m = 4; m >= 1; m >>= 1) {
        const bool up = (ll & m) != 0;
#pragma unroll
        for (int t = 0; t < m; t++) {
            float send = up ? q[t] : q[t + m];
            float recv = __shfl_xor_sync(0xffffffffu, send, m);
            q[t] = (up ? q[t + m] : q[t]) + recv;
        }
    }
    return q[0];
}

// per-row epilogue; runs on the last-arriving warp of the row (R12 lr_epi body)
__device__ __forceinline__ void run_epilogue(
    int b, const float* __restrict__ tree,
    const int* __restrict__ aidx, const int* __restrict__ pidx,
    const int* __restrict__ nidx, float* __restrict__ out, int lane)
{
    // gather chain (dependent loads; issued before the d-reads)
    const int ai    = __ldg(aidx + b);
    const int colme = (lane == 0) ? __ldg(pidx + b) : __ldg(nidx + b * K_ + lane - 1);
    const int col32 = __ldg(nidx + b * K_ + 31);
    const float* __restrict__ trow = tree + (size_t)ai * V_;
    const float tme = __ldg(trow + colme);
    const float t32 = __ldg(trow + col32);

    // distances written by other SMs -> bypass L1
    const float dme = __ldcg(g_d + b * 33 + lane);
    const float d32 = __ldcg(g_d + b * 33 + 32);

    const float maxt   = fmaxf(warp_max(tme), t32);
    const float inv_mt = __fdividef(1.0f, maxt + 1e-6f);
    const float relme  = (maxt - tme + 1e-6f) * inv_mt;
    const float rel32  = (maxt - t32 + 1e-6f) * inv_mt;

    int rank = 1, rr = 0;
#pragma unroll
    for (int o = 1; o < 32; o++) {
        const int j = (lane + o) & 31;
        const float dj = __shfl_sync(0xffffffffu, dme,   j);
        const float rj = __shfl_sync(0xffffffffu, relme, j);
        rank += (dj < dme)   || (dj == dme   && j < lane);
        rr   += (rj > relme) || (rj == relme && j < lane);
    }
    rank += (d32 < dme);
    rr   += (rel32 > relme);

    const int rank32 = 1 + (int)__reduce_add_sync(0xffffffffu, (unsigned)(dme <= d32));
    const int rr32   =     (int)__reduce_add_sync(0xffffffffu, (unsigned)(relme >= rel32));

    const float cme = (rank   <= KTOP) ? inv_log2((float)(rank   + 1)) : 0.0f;
    const float c32 = (rank32 <= KTOP) ? inv_log2((float)(rank32 + 1)) : 0.0f;

    float ic = (rr < KTOP) ? relme * inv_log2((float)(rr + 2)) : 0.0f;
    if (lane == 0 && rr32 < KTOP) ic += rel32 * inv_log2((float)(rr32 + 2));
    const float idcg = warp_sum(ic);
    const float inv_idcg = (idcg > 0.0f) ? __fdividef(1.0f, idcg) : 0.0f;

    float acc = 0.0f;
#pragma unroll
    for (int o = 1; o <= 16; o++) {
        const int j = (lane + o) & 31;
        const float rj = __shfl_sync(0xffffffffu, relme, j);
        const float cj = __shfl_sync(0xffffffffu, cme,   j);
        const float dj = __shfl_sync(0xffffffffu, dme,   j);
        const float t  = pair_term(relme, cme, dme, rj, cj, dj, inv_idcg);
        acc += (o == 16) ? 0.5f * t : t;
    }
    acc += pair_term(relme, cme, dme, rel32, c32, d32, inv_idcg);
    acc = warp_sum(acc);

    if (lane == 0) __stcg(g_loss + b, acc);
    __threadfence();

    // chunk completion (64 rows per chunk)
    const int c = b >> 6;
    int pc = 0;
    if (lane == 0) pc = atomicAdd(&g_chunkcnt[c], 1);
    pc = __shfl_sync(0xffffffffu, pc, 0);
    if (pc == 63) {
        if (lane == 0) g_chunkcnt[c] = 0;        // self-reset for replay
        __threadfence();
        const int base = c * 64;
        float v = __ldcg(g_loss + base + lane) + __ldcg(g_loss + base + 32 + lane);
        v = warp_sum(v);
        if (lane == 0) __stcg(g_chunk + c, v);
        __threadfence();
        int pf = 0;
        if (lane == 0) pf = atomicAdd(&g_ccnt, 1);
        pf = __shfl_sync(0xffffffffu, pf, 0);
        if (pf == NCHUNK - 1) {
            if (lane == 0) g_ccnt = 0;           // self-reset
            __threadfence();
            float s = 0.0f;
#pragma unroll
            for (int t = 0; t < 4; t++) s += __ldcg(g_chunk + t * 32 + lane);
            s = warp_sum(s);
            if (lane == 0) out[0] = WEIGHT_ * s / (float)B_;
        }
    }
}

__global__ void __launch_bounds__(NTHR, 5) lr_persist(
    const float* __restrict__ anchor,
    const float* __restrict__ positive,
    const float* __restrict__ negative,
    const float* __restrict__ tree,
    const int*   __restrict__ aidx,
    const int*   __restrict__ pidx,
    const int*   __restrict__ nidx,
    float*       __restrict__ out)
{
    const int lane = threadIdx.x & 31;
    const int ll   = lane & 7;
    const int wgid = blockIdx.x * (NTHR / 32) + (threadIdx.x >> 5);

    for (int item = wgid; item < NITEM; item += NWARP) {
        const int b = item >> 2;
        const int g = item & 3;

        const float* __restrict__ arow = anchor   + (size_t)b * D_;
        const float* __restrict__ pb   = positive + (size_t)b * D_;
        const float* __restrict__ nb   = negative + (size_t)b * K_ * D_;

        // anchor regs, sign-flipped for c>=1: sum(ah_c*v_c) = -lorentz_inner
        const float ah0 = (lane == 0) ? arow[0] : -arow[lane];
        const float ah1 = -arow[lane + 32];
        const float ah2 = -arow[lane + 64];
        const float ah3 = -arow[lane + 96];
        const float a128n = -arow[128];

        // burst: 8 item partials (+ item 32 for g==3)
        float q[8];
#pragma unroll
        for (int k = 0; k < 8; k++) {
            const int t = 8 * g + k;
            const float* v = (t == 0) ? pb : (nb + (t - 1) * D_);
            q[k] = fmaf(ah0, __ldcs(v + lane), fmaf(ah1, __ldcs(v + lane + 32),
                   fmaf(ah2, __ldcs(v + lane + 64), ah3 * __ldcs(v + lane + 96))));
        }
        float p32 = 0.0f, e32 = 0.0f;
        if (g == 3) {
            const float* v = nb + 31 * D_;
            p32 = fmaf(ah0, __ldcs(v + lane), fmaf(ah1, __ldcs(v + lane + 32),
                  fmaf(ah2, __ldcs(v + lane + 64), ah3 * __ldcs(v + lane + 96))));
            e32 = __ldcs(v + 128);
        }
        // element-128 tail for item (8g + ll); replicated octets hit L1
        const int tl = 8 * g + ll;
        const float e128 = __ldcs(((tl == 0) ? pb : (nb + (tl - 1) * D_)) + 128);

        const float dsum = tile_reduce8(q, lane) + a128n * e128;
        const float dval = acoshd(dsum);
        if (lane < 8) __stcg(g_d + b * 33 + 8 * g + lane, dval);
        if (g == 3) {
            const float s32 = warp_sum(p32) + a128n * e32;
            if (lane == 0) __stcg(g_d + b * 33 + 32, acoshd(s32));
        }
        __threadfence();

        // per-row completion: last of 4 group-warps runs the epilogue
        int prev = 0;
        if (lane == 0) prev = atomicAdd(&g_rowcnt[b], 1);
        prev = __shfl_sync(0xffffffffu, prev, 0);
        if (prev == 3) {
            if (lane == 0) g_rowcnt[b] = 0;      // self-reset for replay
            __threadfence();
            run_epilogue(b, tree, aidx, pidx, nidx, out, lane);
        }
    }
}

extern "C" void kernel_launch(void* const* d_in, const int* in_sizes, int n_in,
                              void* d_out, int out_size)
{
    const float* anchor   = (const float*)d_in[0];
    const float* positive = (const float*)d_in[1];
    const float* negative = (const float*)d_in[2];
    const float* tree     = (const float*)d_in[3];
    const int*   aidx     = (const int*)d_in[4];
    const int*   pidx     = (const int*)d_in[5];
    const int*   nidx     = (const int*)d_in[6];

    lr_persist<<<NBLK, NTHR>>>(anchor, positive, negative, tree,
                               aidx, pidx, nidx, (float*)d_out);
}

// round 15
// speedup vs baseline: 1.8265x; 1.8265x over previous
#include <cuda_runtime.h>

constexpr int B_ = 8192;
constexpr int K_ = 32;
constexpr int D_ = 129;
constexpr int V_ = 2048;
constexpr int KTOP = 10;
constexpr float WEIGHT_ = 0.15f;
constexpr int NCHUNK = 128;          // 64 rows per chunk

__device__ float g_loss[B_];
__device__ float g_chunk[NCHUNK];
__device__ int   g_chunkcnt[NCHUNK];
__device__ int   g_ccnt;

__device__ __forceinline__ float warp_sum(float v) {
#pragma unroll
    for (int o = 16; o; o >>= 1) v += __shfl_xor_sync(0xffffffffu, v, o);
    return v;
}
__device__ __forceinline__ float warp_max(float v) {
#pragma unroll
    for (int o = 16; o; o >>= 1) v = fmaxf(v, __shfl_xor_sync(0xffffffffu, v, o));
    return v;
}
__device__ __forceinline__ float acoshd(float x) {
    x = fmaxf(x, 1.0f + 1e-7f);
    return __logf(x + sqrtf(fmaf(x, x, -1.0f)));
}
__device__ __forceinline__ float inv_log2(float n) {
    return __fdividef(1.0f, __log2f(n));
}
__device__ __forceinline__ float pair_term(float ri, float ci, float di,
                                           float rj, float cj, float dj,
                                           float inv_idcg) {
    float drel  = ri - rj;
    float delta = fabsf(drel * (ci - cj)) * inv_idcg;
    float dd    = dj - di;
    float s     = (drel > 0.0f) ? 1.0f : -1.0f;
    float x     = s * dd;
    float sig   = __fdividef(1.0f, 1.0f + __expf(-x));
    return s * delta * sig * (-dd);
}

// 8-item tile: fold 32->8 lanes, transpose-reduce; returns total of item
// (lane & 7), replicated across the four octets. (verified exact R5/R11/R12)
__device__ __forceinline__ float tile_reduce8(float q[8], int lane) {
#pragma unroll
    for (int k = 0; k < 8; k++) {
        q[k] += __shfl_xor_sync(0xffffffffu, q[k], 16);
        q[k] += __shfl_xor_sync(0xffffffffu, q[k], 8);
    }
    const int ll = lane & 7;
#pragma unroll
    for (int m = 4; m >= 1; m >>= 1) {
        const bool up = (ll & m) != 0;
#pragma unroll
        for (int t = 0; t < m; t++) {
            float send = up ? q[t] : q[t + m];
            float recv = __shfl_xor_sync(0xffffffffu, send, m);
            q[t] = (up ? q[t + m] : q[t]) + recv;
        }
    }
    return q[0];
}

__global__ void __launch_bounds__(128, 10) lr_fused(
    const float* __restrict__ anchor,
    const float* __restrict__ positive,
    const float* __restrict__ negative,
    const float* __restrict__ tree,
    const int*   __restrict__ aidx,
    const int*   __restrict__ pidx,
    const int*   __restrict__ nidx,
    float*       __restrict__ out)
{
    __shared__ float sd[36];             // d[0..32] for this block's row

    const int w    = threadIdx.x >> 5;   // group g = warp id (0..3)
    const int lane = threadIdx.x & 31;
    const int ll   = lane & 7;
    const int b    = blockIdx.x;
    const int g    = w;

    const float* __restrict__ arow = anchor   + (size_t)b * D_;
    const float* __restrict__ pb   = positive + (size_t)b * D_;
    const float* __restrict__ nb   = negative + (size_t)b * K_ * D_;

    // epilogue warp's gather chain: issue first (hidden under all bursts)
    int colme = 0, col32 = 0;
    const float* trow = tree;
    if (g == 0) {
        const int ai = __ldg(aidx + b);
        colme = (lane == 0) ? __ldg(pidx + b) : __ldg(nidx + b * K_ + lane - 1);
        col32 = __ldg(nidx + b * K_ + 31);
        trow  = tree + (size_t)ai * V_;
    }

    // anchor regs, sign-flipped for c>=1: sum(ah_c * v_c) = -lorentz_inner
    const float ah0 = (lane == 0) ? arow[0] : -arow[lane];
    const float ah1 = -arow[lane + 32];
    const float ah2 = -arow[lane + 64];
    const float ah3 = -arow[lane + 96];
    const float a128n = -arow[128];

    // ===== streaming burst: 8 item partials (+ item 32 for g==3) =====
    float q[8];
#pragma unroll
    for (int k = 0; k < 8; k++) {
        const int t = 8 * g + k;
        const float* v = (t == 0) ? pb : (nb + (t - 1) * D_);
        q[k] = fmaf(ah0, __ldcs(v + lane), fmaf(ah1, __ldcs(v + lane + 32),
               fmaf(ah2, __ldcs(v + lane + 64), ah3 * __ldcs(v + lane + 96))));
    }
    float p32 = 0.0f, e32 = 0.0f;
    if (g == 3) {
        const float* v = nb + 31 * D_;
        p32 = fmaf(ah0, __ldcs(v + lane), fmaf(ah1, __ldcs(v + lane + 32),
              fmaf(ah2, __ldcs(v + lane + 64), ah3 * __ldcs(v + lane + 96))));
        e32 = __ldcs(v + 128);
    }
    float tme = 0.0f, t32 = 0.0f;
    if (g == 0) {                         // tree gather under the burst
        tme = __ldg(trow + colme);
        t32 = __ldg(trow + col32);
    }
    // element-128 tail for item (8g + ll); replicated octets hit L1
    const int tl = 8 * g + ll;
    const float e128 = __ldcs(((tl == 0) ? pb : (nb + (tl - 1) * D_)) + 128);

    const float dsum = tile_reduce8(q, lane) + a128n * e128;
    const float dval = acoshd(dsum);
    if (lane < 8) sd[8 * g + lane] = dval;
    if (g == 3) {
        const float s32 = warp_sum(p32) + a128n * e32;
        if (lane == 0) sd[32] = acoshd(s32);
    }
    __threadfence_block();

    // ===== producer warps arrive & exit; warp 0 syncs and runs epilogue =====
    if (g != 0) {
        asm volatile("bar.arrive 1, 128;" ::: "memory");
        return;
    }
    asm volatile("bar.sync 1, 128;" ::: "memory");

    const float dme = sd[lane];
    const float d32 = sd[32];

    const float maxt   = fmaxf(warp_max(tme), t32);
    const float inv_mt = __fdividef(1.0f, maxt + 1e-6f);
    const float relme  = (maxt - tme + 1e-6f) * inv_mt;
    const float rel32  = (maxt - t32 + 1e-6f) * inv_mt;

    // stable ranks via lane rotation
    int rank = 1, rr = 0;
#pragma unroll
    for (int o = 1; o < 32; o++) {
        const int j = (lane + o) & 31;
        const float dj = __shfl_sync(0xffffffffu, dme,   j);
        const float rj = __shfl_sync(0xffffffffu, relme, j);
        rank += (dj < dme)   || (dj == dme   && j < lane);
        rr   += (rj > relme) || (rj == relme && j < lane);
    }
    rank += (d32 < dme);
    rr   += (rel32 > relme);

    const int rank32 = 1 + (int)__reduce_add_sync(0xffffffffu, (unsigned)(dme <= d32));
    const int rr32   =     (int)__reduce_add_sync(0xffffffffu, (unsigned)(relme >= rel32));

    const float cme = (rank   <= KTOP) ? inv_log2((float)(rank   + 1)) : 0.0f;
    const float c32 = (rank32 <= KTOP) ? inv_log2((float)(rank32 + 1)) : 0.0f;

    float ic = (rr < KTOP) ? relme * inv_log2((float)(rr + 2)) : 0.0f;
    if (lane == 0 && rr32 < KTOP) ic += rel32 * inv_log2((float)(rr32 + 2));
    const float idcg = warp_sum(ic);
    const float inv_idcg = (idcg > 0.0f) ? __fdividef(1.0f, idcg) : 0.0f;

    // pairwise lambda: rotation covers C(32,2); o=16 double-counted
    float acc = 0.0f;
#pragma unroll
    for (int o = 1; o <= 16; o++) {
        const int j = (lane + o) & 31;
        const float rj = __shfl_sync(0xffffffffu, relme, j);
        const float cj = __shfl_sync(0xffffffffu, cme,   j);
        const float dj = __shfl_sync(0xffffffffu, dme,   j);
        const float t  = pair_term(relme, cme, dme, rj, cj, dj, inv_idcg);
        acc += (o == 16) ? 0.5f * t : t;
    }
    acc += pair_term(relme, cme, dme, rel32, c32, d32, inv_idcg);
    acc = warp_sum(acc);

    // ===== deterministic fenced completion tree (64 rows/chunk, then 128 chunks) =====
    if (lane == 0) __stcg(g_loss + b, acc);
    __threadfence();

    const int c = b >> 6;
    int pc = 0;
    if (lane == 0) pc = atomicAdd(&g_chunkcnt[c], 1);
    pc = __shfl_sync(0xffffffffu, pc, 0);
    if (pc == 63) {
        if (lane == 0) g_chunkcnt[c] = 0;        // self-reset for graph replay
        __threadfence();
        const int base = c * 64;
        float v = __ldcg(g_loss + base + lane) + __ldcg(g_loss + base + 32 + lane);
        v = warp_sum(v);
        if (lane == 0) __stcg(g_chunk + c, v);
        __threadfence();
        int pf = 0;
        if (lane == 0) pf = atomicAdd(&g_ccnt, 1);
        pf = __shfl_sync(0xffffffffu, pf, 0);
        if (pf == NCHUNK - 1) {
            if (lane == 0) g_ccnt = 0;           // self-reset
            __threadfence();
            float s = 0.0f;
#pragma unroll
            for (int t = 0; t < 4; t++) s += __ldcg(g_chunk + t * 32 + lane);
            s = warp_sum(s);
            if (lane == 0) out[0] = WEIGHT_ * s / (float)B_;
        }
    }
}

extern "C" void kernel_launch(void* const* d_in, const int* in_sizes, int n_in,
                              void* d_out, int out_size)
{
    const float* anchor   = (const float*)d_in[0];
    const float* positive = (const float*)d_in[1];
    const float* negative = (const float*)d_in[2];
    const float* tree     = (const float*)d_in[3];
    const int*   aidx     = (const int*)d_in[4];
    const int*   pidx     = (const int*)d_in[5];
    const int*   nidx     = (const int*)d_in[6];

    lr_fused<<<B_, 128>>>(anchor, positive, negative, tree,
                          aidx, pidx, nidx, (float*)d_out);
}